// round 9
// baseline (speedup 1.0000x reference)
#include <cuda_runtime.h>
#include <cstdint>

// ---------------- problem constants ----------------
#define HWPIX   (1024*1024)      // H*W
#define BATCH   4
#define CIN     3
#define NH      25               // MAXH
#define DEPTH   6

// Weight layout, all entries (w,w)-duplicated u64:
// CONST part (cW, 828 ulls):
//   win      : 25 rows x 4 slots  -> o*4 + c                 [0,   100)
//   ws[d=0]  : 25 rows x 26 slots -> 100 + o*26 + c          [100, 750)
//   wout     : 3 rows x 26 slots  -> 750 + o*26 + c          [750, 828)
// SMEM part (staged from g_wdup+828, 3250 ulls):
//   ws[d=1..5]: ((d-1)*25+o)*26 + c                          [0, 3250)
#define CW_ULLS  828
#define SM_ULLS  3250
#define G_ULLS   (CW_ULLS + SM_ULLS)   // 4078

__constant__ unsigned long long cW[CW_ULLS];
__device__   unsigned long long g_wdup[G_ULLS];

typedef unsigned long long ull;

// ---------------- f32x2 helpers (Blackwell packed fp32) ----------------
__device__ __forceinline__ ull d_mul2(ull a, ull b) {
    ull d; asm("mul.rn.f32x2 %0, %1, %2;" : "=l"(d) : "l"(a), "l"(b)); return d;
}
__device__ __forceinline__ ull d_add2(ull a, ull b) {
    ull d; asm("add.rn.f32x2 %0, %1, %2;" : "=l"(d) : "l"(a), "l"(b)); return d;
}
__device__ __forceinline__ ull d_fma2(ull a, ull b, ull c) {
    ull d; asm("fma.rn.f32x2 %0, %1, %2, %3;" : "=l"(d) : "l"(a), "l"(b), "l"(c)); return d;
}
__device__ __forceinline__ void unpack2(ull v, float& a, float& b) {
    asm("mov.b64 {%0, %1}, %2;" : "=f"(a), "=f"(b) : "l"(v));
}
__device__ __forceinline__ ull pack2(float a, float b) {
    ull r; asm("mov.b64 %0, {%1, %2};" : "=l"(r) : "f"(a), "f"(b)); return r;
}
__device__ __forceinline__ ull bcast2(float f) {
    unsigned u = __float_as_uint(f);
    return ((ull)u << 32) | (ull)u;
}
__device__ __forceinline__ float d_ex2(float x) {
    float r; asm("ex2.approx.f32 %0, %1;" : "=f"(r) : "f"(x)); return r;
}
__device__ __forceinline__ float d_rcp(float x) {
    float r; asm("rcp.approx.f32 %0, %1;" : "=f"(r) : "f"(x)); return r;
}
__device__ __forceinline__ float d_tanh(float x) {
    float r; asm("tanh.approx.f32 %0, %1;" : "=f"(r) : "f"(x)); return r;
}

// tanh on a pixel pair via MUFU.TANH (rel_err ~1.5e-6 measured end-to-end)
__device__ __forceinline__ ull tanh2(ull v) {
    float a, b; unpack2(v, a, b);
    return pack2(d_tanh(a), d_tanh(b));
}

// sigmoid on a pixel pair (precise path, only 3 per thread)
__device__ __forceinline__ ull sigmoid2(ull v) {
    ull s = d_mul2(v, bcast2(-1.4426950408889634f));  // -log2(e)
    float s0, s1; unpack2(s, s0, s1);
    ull den = d_add2(pack2(d_ex2(s0), d_ex2(s1)), bcast2(1.0f));
    float dn0, dn1; unpack2(den, dn0, dn1);
    return pack2(d_rcp(dn0), d_rcp(dn1));
}

// ---------------- prep: duplicate weights into padded (w,w) layout ----------------
__global__ void prep_weights(const float* __restrict__ win,
                             const float* __restrict__ ws,
                             const float* __restrict__ wout) {
    int i = blockIdx.x * blockDim.x + threadIdx.x;
    if (i >= G_ULLS) return;
    float w = 0.0f;
    if (i < 100) {                       // win
        int o = i >> 2, c = i & 3;
        if (c < CIN) w = win[o * CIN + c];
    } else if (i < 750) {                // ws layer 0
        int j = i - 100;
        int o = j / 26, c = j % 26;
        if (c < NH) w = ws[o * NH + c];
    } else if (i < CW_ULLS) {            // wout
        int j = i - 750;
        int o = j / 26, c = j % 26;
        if (c < NH) w = wout[o * NH + c];
    } else {                             // ws layers 1..5
        int j = i - CW_ULLS;
        int row = NH + j / 26;           // global row in [25,150)
        int c = j % 26;
        if (c < NH) w = ws[row * NH + c];
    }
    unsigned u = __float_as_uint(w);
    g_wdup[i] = ((ull)u << 32) | (ull)u;
}

// ---------------- dot-product rows (dual accumulators for ILP) ----------------
__device__ __forceinline__ ull row_dot_c(int base, const ull (&h)[NH]) {
    ulonglong2 w0 = *(const ulonglong2*)&cW[base];
    ull a0 = d_mul2(w0.x, h[0]);
    ull a1 = d_mul2(w0.y, h[1]);
    #pragma unroll
    for (int cc = 1; cc < 12; cc++) {
        ulonglong2 w = *(const ulonglong2*)&cW[base + 2 * cc];
        a0 = d_fma2(w.x, h[2 * cc],     a0);
        a1 = d_fma2(w.y, h[2 * cc + 1], a1);
    }
    a0 = d_fma2(cW[base + 24], h[24], a0);
    return d_add2(a0, a1);
}

__device__ __forceinline__ ull row_dot_s(const ull* __restrict__ base, const ull (&h)[NH]) {
    ulonglong2 w0 = *(const ulonglong2*)base;
    ull a0 = d_mul2(w0.x, h[0]);
    ull a1 = d_mul2(w0.y, h[1]);
    #pragma unroll
    for (int cc = 1; cc < 12; cc++) {
        ulonglong2 w = *(const ulonglong2*)(base + 2 * cc);
        a0 = d_fma2(w.x, h[2 * cc],     a0);
        a1 = d_fma2(w.y, h[2 * cc + 1], a1);
    }
    a0 = d_fma2(base[24], h[24], a0);
    return d_add2(a0, a1);
}

__device__ __forceinline__ void layer_c(int lbase, const ull (&src)[NH], ull (&dst)[NH]) {
    #pragma unroll
    for (int o = 0; o < NH; o++)
        dst[o] = tanh2(row_dot_c(lbase + o * 26, src));
}

__device__ __forceinline__ void layer_s(const ull* __restrict__ lw,
                                        const ull (&src)[NH], ull (&dst)[NH]) {
    #pragma unroll
    for (int o = 0; o < NH; o++)
        dst[o] = tanh2(row_dot_s(lw + o * 26, src));
}

// ---------------- main kernel ----------------
// 448 threads (14 warps/SM): 448 * ~130 regs = 58.2K < 64K regfile, and the
// per-thread cap (65536/448 = 146) leaves headroom over the ~130 needed, so
// NO spills (the round-8 failure mode). One resident block per SM, persistent.
#define NBLOCKS  148
#define NTHREADS 448

__global__ void __launch_bounds__(NTHREADS)
simplenet_kernel(const float* __restrict__ x, float* __restrict__ out) {
    __shared__ ull sW[SM_ULLS];          // 26 KB: hidden layers 1..5

    // Stage smem weights once per block (g_wdup is L2-resident)
    for (int i = threadIdx.x; i < SM_ULLS; i += NTHREADS)
        sW[i] = g_wdup[CW_ULLS + i];
    __syncthreads();

    const int pairs  = BATCH * (HWPIX / 2);          // 2,097,152
    const int stride = NBLOCKS * NTHREADS;

    for (int t = blockIdx.x * NTHREADS + threadIdx.x; t < pairs; t += stride) {
        int b  = t >> 19;                            // HWPIX/2 = 2^19 pairs/image
        int hp = t & ((HWPIX >> 1) - 1);

        const float* xb = x + (size_t)b * (CIN * HWPIX) + ((size_t)hp << 1);
        ull x0 = *(const ull*)(xb);
        ull x1 = *(const ull*)(xb + HWPIX);
        ull x2 = *(const ull*)(xb + 2 * HWPIX);

        ull h[NH], hn[NH];

        // ---- input layer: 3 -> 25, tanh (const port) ----
        #pragma unroll
        for (int o = 0; o < NH; o++) {
            ulonglong2 w01 = *(const ulonglong2*)&cW[o * 4];
            ull w2 = cW[o * 4 + 2];
            ull acc = d_mul2(w01.x, x0);
            acc = d_fma2(w01.y, x1, acc);
            acc = d_fma2(w2,    x2, acc);
            h[o] = tanh2(acc);
        }

        // ---- hidden layer 0 (const port) ----
        layer_c(100, h, hn);
        // ---- hidden layers 1..5 (shared-mem port), ping-pong ----
        layer_s(sW +    0, hn, h);
        layer_s(sW +  650, h, hn);
        layer_s(sW + 1300, hn, h);
        layer_s(sW + 1950, h, hn);
        layer_s(sW + 2600, hn, h);

        // ---- output layer: 25 -> 3, sigmoid (const port) ----
        float* ob = out + (size_t)b * (CIN * HWPIX) + ((size_t)hp << 1);
        #pragma unroll
        for (int o = 0; o < CIN; o++) {
            ull acc = row_dot_c(750 + o * 26, h);
            *(ull*)(ob + (size_t)o * HWPIX) = sigmoid2(acc);
        }
    }
}

// ---------------- launch ----------------
extern "C" void kernel_launch(void* const* d_in, const int* in_sizes, int n_in,
                              void* d_out, int out_size) {
    const float* x    = (const float*)d_in[0];
    const float* win  = (const float*)d_in[1];
    const float* ws   = (const float*)d_in[2];
    const float* wout = (const float*)d_in[3];
    float* out = (float*)d_out;

    // 1) duplicate weights into padded (w,w) u64 layout
    prep_weights<<<(G_ULLS + 255) / 256, 256>>>(win, ws, wout);

    // 2) stage the const-port share into __constant__
    void* wdup_addr = nullptr;
    cudaGetSymbolAddress(&wdup_addr, g_wdup);
    cudaMemcpyToSymbolAsync(cW, wdup_addr, CW_ULLS * sizeof(unsigned long long),
                            0, cudaMemcpyDeviceToDevice, 0);

    // 3) persistent main compute
    simplenet_kernel<<<NBLOCKS, NTHREADS>>>(x, out);
}

// round 11
// speedup vs baseline: 1.0662x; 1.0662x over previous
#include <cuda_runtime.h>
#include <cstdint>

// ---------------- problem constants ----------------
#define HWPIX   (1024*1024)      // H*W
#define BATCH   4
#define CIN     3
#define NH      25               // MAXH
#define DEPTH   6

// Weight layout, all entries (w,w)-duplicated u64:
// CONST part (cW, 828 ulls):
//   win      : 25 rows x 4 slots  -> o*4 + c                 [0,   100)
//   ws[d=0]  : 25 rows x 26 slots -> 100 + o*26 + c          [100, 750)
//   wout     : 3 rows x 26 slots  -> 750 + o*26 + c          [750, 828)
// SMEM part (staged from g_wdup+828, 3250 ulls):
//   ws[d=1..5]: ((d-1)*25+o)*26 + c                          [0, 3250)
#define CW_ULLS  828
#define SM_ULLS  3250
#define G_ULLS   (CW_ULLS + SM_ULLS)   // 4078

__constant__ unsigned long long cW[CW_ULLS];
__device__   unsigned long long g_wdup[G_ULLS];

typedef unsigned long long ull;

// ---------------- f32x2 helpers (Blackwell packed fp32) ----------------
__device__ __forceinline__ ull d_mul2(ull a, ull b) {
    ull d; asm("mul.rn.f32x2 %0, %1, %2;" : "=l"(d) : "l"(a), "l"(b)); return d;
}
__device__ __forceinline__ ull d_add2(ull a, ull b) {
    ull d; asm("add.rn.f32x2 %0, %1, %2;" : "=l"(d) : "l"(a), "l"(b)); return d;
}
__device__ __forceinline__ ull d_fma2(ull a, ull b, ull c) {
    ull d; asm("fma.rn.f32x2 %0, %1, %2, %3;" : "=l"(d) : "l"(a), "l"(b), "l"(c)); return d;
}
__device__ __forceinline__ void unpack2(ull v, float& a, float& b) {
    asm("mov.b64 {%0, %1}, %2;" : "=f"(a), "=f"(b) : "l"(v));
}
__device__ __forceinline__ ull pack2(float a, float b) {
    ull r; asm("mov.b64 %0, {%1, %2};" : "=l"(r) : "f"(a), "f"(b)); return r;
}
__device__ __forceinline__ ull bcast2(float f) {
    unsigned u = __float_as_uint(f);
    return ((ull)u << 32) | (ull)u;
}
__device__ __forceinline__ float d_ex2(float x) {
    float r; asm("ex2.approx.f32 %0, %1;" : "=f"(r) : "f"(x)); return r;
}
__device__ __forceinline__ float d_rcp(float x) {
    float r; asm("rcp.approx.f32 %0, %1;" : "=f"(r) : "f"(x)); return r;
}
__device__ __forceinline__ float d_tanh(float x) {
    float r; asm("tanh.approx.f32 %0, %1;" : "=f"(r) : "f"(x)); return r;
}

// tanh on a pixel pair via MUFU.TANH (rel_err ~1.5e-6 measured end-to-end)
__device__ __forceinline__ ull tanh2(ull v) {
    float a, b; unpack2(v, a, b);
    return pack2(d_tanh(a), d_tanh(b));
}

// sigmoid on a pixel pair (precise path, only 3 per thread)
__device__ __forceinline__ ull sigmoid2(ull v) {
    ull s = d_mul2(v, bcast2(-1.4426950408889634f));  // -log2(e)
    float s0, s1; unpack2(s, s0, s1);
    ull den = d_add2(pack2(d_ex2(s0), d_ex2(s1)), bcast2(1.0f));
    float dn0, dn1; unpack2(den, dn0, dn1);
    return pack2(d_rcp(dn0), d_rcp(dn1));
}

// ---------------- prep: duplicate weights into padded (w,w) layout ----------------
__global__ void prep_weights(const float* __restrict__ win,
                             const float* __restrict__ ws,
                             const float* __restrict__ wout) {
    int i = blockIdx.x * blockDim.x + threadIdx.x;
    if (i >= G_ULLS) return;
    float w = 0.0f;
    if (i < 100) {                       // win
        int o = i >> 2, c = i & 3;
        if (c < CIN) w = win[o * CIN + c];
    } else if (i < 750) {                // ws layer 0
        int j = i - 100;
        int o = j / 26, c = j % 26;
        if (c < NH) w = ws[o * NH + c];
    } else if (i < CW_ULLS) {            // wout
        int j = i - 750;
        int o = j / 26, c = j % 26;
        if (c < NH) w = wout[o * NH + c];
    } else {                             // ws layers 1..5
        int j = i - CW_ULLS;
        int row = NH + j / 26;           // global row in [25,150)
        int c = j % 26;
        if (c < NH) w = ws[row * NH + c];
    }
    unsigned u = __float_as_uint(w);
    g_wdup[i] = ((ull)u << 32) | (ull)u;
}

// ---------------- dot-product rows (dual accumulators for ILP) ----------------
__device__ __forceinline__ ull row_dot_c(int base, const ull (&h)[NH]) {
    ulonglong2 w0 = *(const ulonglong2*)&cW[base];
    ull a0 = d_mul2(w0.x, h[0]);
    ull a1 = d_mul2(w0.y, h[1]);
    #pragma unroll
    for (int cc = 1; cc < 12; cc++) {
        ulonglong2 w = *(const ulonglong2*)&cW[base + 2 * cc];
        a0 = d_fma2(w.x, h[2 * cc],     a0);
        a1 = d_fma2(w.y, h[2 * cc + 1], a1);
    }
    a0 = d_fma2(cW[base + 24], h[24], a0);
    return d_add2(a0, a1);
}

__device__ __forceinline__ ull row_dot_s(const ull* __restrict__ base, const ull (&h)[NH]) {
    ulonglong2 w0 = *(const ulonglong2*)base;
    ull a0 = d_mul2(w0.x, h[0]);
    ull a1 = d_mul2(w0.y, h[1]);
    #pragma unroll
    for (int cc = 1; cc < 12; cc++) {
        ulonglong2 w = *(const ulonglong2*)(base + 2 * cc);
        a0 = d_fma2(w.x, h[2 * cc],     a0);
        a1 = d_fma2(w.y, h[2 * cc + 1], a1);
    }
    a0 = d_fma2(base[24], h[24], a0);
    return d_add2(a0, a1);
}

__device__ __forceinline__ void layer_c(int lbase, const ull (&src)[NH], ull (&dst)[NH]) {
    #pragma unroll
    for (int o = 0; o < NH; o++)
        dst[o] = tanh2(row_dot_c(lbase + o * 26, src));
}

__device__ __forceinline__ void layer_s(const ull* __restrict__ lw,
                                        const ull (&src)[NH], ull (&dst)[NH]) {
    #pragma unroll
    for (int o = 0; o < NH; o++)
        dst[o] = tanh2(row_dot_s(lw + o * 26, src));
}

// ---------------- main kernel ----------------
// 128-thread blocks: launch_bounds(128) => per-thread reg cap = 512, so ptxas
// CANNOT be forced to spill (rounds 8/9 failure: u64 pair-alignment pushed true
// demand above the 128/144 caps). Occupancy from multiple resident blocks:
// at <=170 regs/thread, 3 blocks/SM = 12 warps. Persistent grid 3*148.
#define NTHREADS 128
#define NBLOCKS  (148 * 3)

__global__ void __launch_bounds__(NTHREADS)
simplenet_kernel(const float* __restrict__ x, float* __restrict__ out) {
    __shared__ ull sW[SM_ULLS];          // 26 KB: hidden layers 1..5

    // Stage smem weights once per block (g_wdup is L2-resident)
    for (int i = threadIdx.x; i < SM_ULLS; i += NTHREADS)
        sW[i] = g_wdup[CW_ULLS + i];
    __syncthreads();

    const int pairs  = BATCH * (HWPIX / 2);          // 2,097,152
    const int stride = NBLOCKS * NTHREADS;

    for (int t = blockIdx.x * NTHREADS + threadIdx.x; t < pairs; t += stride) {
        int b  = t >> 19;                            // HWPIX/2 = 2^19 pairs/image
        int hp = t & ((HWPIX >> 1) - 1);

        const float* xb = x + (size_t)b * (CIN * HWPIX) + ((size_t)hp << 1);
        ull x0 = *(const ull*)(xb);
        ull x1 = *(const ull*)(xb + HWPIX);
        ull x2 = *(const ull*)(xb + 2 * HWPIX);

        ull h[NH], hn[NH];

        // ---- input layer: 3 -> 25, tanh (const port) ----
        #pragma unroll
        for (int o = 0; o < NH; o++) {
            ulonglong2 w01 = *(const ulonglong2*)&cW[o * 4];
            ull w2 = cW[o * 4 + 2];
            ull acc = d_mul2(w01.x, x0);
            acc = d_fma2(w01.y, x1, acc);
            acc = d_fma2(w2,    x2, acc);
            h[o] = tanh2(acc);
        }

        // ---- hidden layer 0 (const port) ----
        layer_c(100, h, hn);
        // ---- hidden layers 1..5 (shared-mem port), ping-pong ----
        layer_s(sW +    0, hn, h);
        layer_s(sW +  650, h, hn);
        layer_s(sW + 1300, hn, h);
        layer_s(sW + 1950, h, hn);
        layer_s(sW + 2600, hn, h);

        // ---- output layer: 25 -> 3, sigmoid (const port) ----
        float* ob = out + (size_t)b * (CIN * HWPIX) + ((size_t)hp << 1);
        #pragma unroll
        for (int o = 0; o < CIN; o++) {
            ull acc = row_dot_c(750 + o * 26, h);
            *(ull*)(ob + (size_t)o * HWPIX) = sigmoid2(acc);
        }
    }
}

// ---------------- launch ----------------
extern "C" void kernel_launch(void* const* d_in, const int* in_sizes, int n_in,
                              void* d_out, int out_size) {
    const float* x    = (const float*)d_in[0];
    const float* win  = (const float*)d_in[1];
    const float* ws   = (const float*)d_in[2];
    const float* wout = (const float*)d_in[3];
    float* out = (float*)d_out;

    // 1) duplicate weights into padded (w,w) u64 layout
    prep_weights<<<(G_ULLS + 255) / 256, 256>>>(win, ws, wout);

    // 2) stage the const-port share into __constant__
    void* wdup_addr = nullptr;
    cudaGetSymbolAddress(&wdup_addr, g_wdup);
    cudaMemcpyToSymbolAsync(cW, wdup_addr, CW_ULLS * sizeof(unsigned long long),
                            0, cudaMemcpyDeviceToDevice, 0);

    // 3) persistent main compute
    simplenet_kernel<<<NBLOCKS, NTHREADS>>>(x, out);
}